// round 1
// baseline (speedup 1.0000x reference)
#include <cuda_runtime.h>
#include <cuda_bf16.h>
#include <math.h>

// ---------------------------------------------------------------------------
// Problem constants (shapes fixed by the dataset)
//   x: (N=2, T=2048, C=512), H=8, hd=64, WIN=63, LEFT=31, hid=2048
// ---------------------------------------------------------------------------
#define C_DIM   512
#define HID_DIM 2048
#define QKV_DIM 1536
#define H_HEADS 8
#define HEAD_D  64
#define WIN     63
#define LEFT    31

#define M_ROWS  4096   // N*T

// ---------------------------------------------------------------------------
// Scratch (static device globals: no allocation allowed)
// ---------------------------------------------------------------------------
__device__ float g_h  [M_ROWS * C_DIM];     // ln1 out, later ln2 out (reused)
__device__ float g_qkv[M_ROWS * QKV_DIM];   // fused q|k|v
__device__ float g_att[M_ROWS * C_DIM];     // attention output
__device__ float g_x2 [M_ROWS * C_DIM];     // shortcut + proj
__device__ float g_m1 [M_ROWS * HID_DIM];   // fc1+gelu out

// ---------------------------------------------------------------------------
// LayerNorm: one block (128 threads) per row of 512 floats
// ---------------------------------------------------------------------------
__global__ __launch_bounds__(128) void ln_kernel(
    const float* __restrict__ x, const float* __restrict__ w,
    const float* __restrict__ b, float* __restrict__ out)
{
    int row = blockIdx.x;
    int tid = threadIdx.x;
    const float4* xr = (const float4*)(x + (size_t)row * C_DIM);
    float4 v = xr[tid];
    float s  = v.x + v.y + v.z + v.w;
    float sq = v.x*v.x + v.y*v.y + v.z*v.z + v.w*v.w;
    #pragma unroll
    for (int o = 16; o > 0; o >>= 1) {
        s  += __shfl_xor_sync(0xffffffffu, s,  o);
        sq += __shfl_xor_sync(0xffffffffu, sq, o);
    }
    __shared__ float ss[4], ssq[4];
    if ((tid & 31) == 0) { ss[tid >> 5] = s; ssq[tid >> 5] = sq; }
    __syncthreads();
    s  = ss[0]  + ss[1]  + ss[2]  + ss[3];
    sq = ssq[0] + ssq[1] + ssq[2] + ssq[3];
    float mu  = s * (1.0f / C_DIM);
    float var = sq * (1.0f / C_DIM) - mu * mu;
    float inv = rsqrtf(var + 1e-5f);
    float4 wv = ((const float4*)w)[tid];
    float4 bv = ((const float4*)b)[tid];
    float4 o;
    o.x = (v.x - mu) * inv * wv.x + bv.x;
    o.y = (v.y - mu) * inv * wv.y + bv.y;
    o.z = (v.z - mu) * inv * wv.z + bv.z;
    o.w = (v.w - mu) * inv * wv.w + bv.w;
    ((float4*)(out + (size_t)row * C_DIM))[tid] = o;
}

// ---------------------------------------------------------------------------
// SGEMM: C[M,N] = A[M,K] @ B[N,K]^T + bias[N] (+res[M,N]) (optional GELU)
// 128x128 tile, BK=8, 256 threads, 8x8 per thread.
// All dims here are multiples of the tile sizes (no bounds checks).
// ---------------------------------------------------------------------------
template<bool RES, bool GELU>
__global__ __launch_bounds__(256) void sgemm_kernel(
    const float* __restrict__ A, const float* __restrict__ B,
    const float* __restrict__ bias, const float* __restrict__ res,
    float* __restrict__ C, int M, int N, int K)
{
    __shared__ __align__(16) float As[8][128];
    __shared__ __align__(16) float Bs[8][128];

    int tid = threadIdx.x;
    int tx = tid & 15;        // 0..15 -> N dir
    int ty = tid >> 4;        // 0..15 -> M dir

    const float* Ab = A + (size_t)blockIdx.y * 128 * K;
    const float* Bb = B + (size_t)blockIdx.x * 128 * K;

    int lrow = tid >> 1;            // 0..127
    int lk   = (tid & 1) << 2;      // 0 or 4

    float acc[8][8];
    #pragma unroll
    for (int i = 0; i < 8; i++)
        #pragma unroll
        for (int j = 0; j < 8; j++) acc[i][j] = 0.0f;

    for (int k0 = 0; k0 < K; k0 += 8) {
        float4 a4 = *(const float4*)(Ab + (size_t)lrow * K + k0 + lk);
        float4 b4 = *(const float4*)(Bb + (size_t)lrow * K + k0 + lk);
        As[lk + 0][lrow] = a4.x; As[lk + 1][lrow] = a4.y;
        As[lk + 2][lrow] = a4.z; As[lk + 3][lrow] = a4.w;
        Bs[lk + 0][lrow] = b4.x; Bs[lk + 1][lrow] = b4.y;
        Bs[lk + 2][lrow] = b4.z; Bs[lk + 3][lrow] = b4.w;
        __syncthreads();

        #pragma unroll
        for (int kk = 0; kk < 8; kk++) {
            float ar[8], br[8];
            *(float4*)(ar)     = *(const float4*)&As[kk][ty * 8];
            *(float4*)(ar + 4) = *(const float4*)&As[kk][ty * 8 + 4];
            *(float4*)(br)     = *(const float4*)&Bs[kk][tx * 8];
            *(float4*)(br + 4) = *(const float4*)&Bs[kk][tx * 8 + 4];
            #pragma unroll
            for (int i = 0; i < 8; i++)
                #pragma unroll
                for (int j = 0; j < 8; j++)
                    acc[i][j] += ar[i] * br[j];
        }
        __syncthreads();
    }

    int row0 = blockIdx.y * 128 + ty * 8;
    int col0 = blockIdx.x * 128 + tx * 8;
    #pragma unroll
    for (int i = 0; i < 8; i++) {
        int row = row0 + i;
        #pragma unroll
        for (int j = 0; j < 8; j++) {
            int col = col0 + j;
            float v = acc[i][j] + bias[col];
            if (RES)  v += res[(size_t)row * N + col];
            if (GELU) v = 0.5f * v * (1.0f + erff(v * 0.70710678118654752f));
            C[(size_t)row * N + col] = v;
        }
    }
}

// ---------------------------------------------------------------------------
// Windowed attention. grid(T, Nbatch), 256 threads = 8 warps (one per head).
// qkv layout per row: [q(512) | k(512) | v(512)], head h occupies [h*64, h*64+64)
// ---------------------------------------------------------------------------
__global__ __launch_bounds__(256) void attn_kernel(
    const float* __restrict__ qkv, const float* __restrict__ rel_bias,
    float* __restrict__ out, int T)
{
    int t = blockIdx.x;
    int n = blockIdx.y;
    int tid  = threadIdx.x;
    int h    = tid >> 5;
    int lane = tid & 31;

    __shared__ __align__(16) float smq[512];
    size_t rowbase = (size_t)n * T + t;
    const float* qrow = qkv + rowbase * QKV_DIM;
    smq[tid]       = qrow[tid]       * 0.125f;   // scale = hd^-0.5
    smq[tid + 256] = qrow[tid + 256] * 0.125f;
    __syncthreads();

    const float4* q4 = (const float4*)(smq + h * HEAD_D);

    // scores: lane owns window positions w = lane and lane+32 (lane<31)
    float p[2];
    float mx = -1e30f;
    #pragma unroll
    for (int i = 0; i < 2; i++) {
        int w = lane + i * 32;
        float sc = -1e30f;
        if (w < WIN) {
            float bias = rel_bias[h * WIN + w];
            int pos = t - LEFT + w;
            if (pos >= 0 && pos < T) {
                const float4* k4 = (const float4*)(qkv +
                    ((size_t)n * T + pos) * QKV_DIM + C_DIM + h * HEAD_D);
                float dot = 0.0f;
                #pragma unroll
                for (int d = 0; d < 16; d++) {
                    float4 kk = k4[d];
                    float4 qq = q4[d];
                    dot += qq.x * kk.x + qq.y * kk.y + qq.z * kk.z + qq.w * kk.w;
                }
                sc = dot + bias;
            } else {
                sc = bias - 100.0f;
            }
        }
        p[i] = sc;
        mx = fmaxf(mx, sc);
    }
    #pragma unroll
    for (int o = 16; o > 0; o >>= 1)
        mx = fmaxf(mx, __shfl_xor_sync(0xffffffffu, mx, o));

    float e0 = expf(p[0] - mx);
    float e1 = (lane < WIN - 32) ? expf(p[1] - mx) : 0.0f;
    float sum = e0 + e1;
    #pragma unroll
    for (int o = 16; o > 0; o >>= 1)
        sum += __shfl_xor_sync(0xffffffffu, sum, o);
    float rinv = 1.0f / sum;
    p[0] = e0 * rinv;
    p[1] = e1 * rinv;

    // out[d] = sum_w attn[w] * v[pos_w, d]; masked pos -> padded v = 0, skip
    float acc0 = 0.0f, acc1 = 0.0f;
    #pragma unroll
    for (int w = 0; w < WIN; w++) {
        float a = __shfl_sync(0xffffffffu, p[w >> 5], w & 31);
        int pos = t - LEFT + w;
        if (pos >= 0 && pos < T) {
            const float* vrow = qkv + ((size_t)n * T + pos) * QKV_DIM
                                + 2 * C_DIM + h * HEAD_D;
            acc0 += a * vrow[lane];
            acc1 += a * vrow[lane + 32];
        }
    }
    float* orow = out + rowbase * C_DIM + h * HEAD_D;
    orow[lane]      = acc0;
    orow[lane + 32] = acc1;
}

// ---------------------------------------------------------------------------
// Launch
// ---------------------------------------------------------------------------
extern "C" void kernel_launch(void* const* d_in, const int* in_sizes, int n_in,
                              void* d_out, int out_size)
{
    const float* x       = (const float*)d_in[0];
    const float* norm1_w = (const float*)d_in[1];
    const float* norm1_b = (const float*)d_in[2];
    const float* qkv_w   = (const float*)d_in[3];
    const float* qkv_b   = (const float*)d_in[4];
    const float* relbias = (const float*)d_in[5];
    const float* proj_w  = (const float*)d_in[6];
    const float* proj_b  = (const float*)d_in[7];
    const float* norm2_w = (const float*)d_in[8];
    const float* norm2_b = (const float*)d_in[9];
    const float* fc1_w   = (const float*)d_in[10];
    const float* fc1_b   = (const float*)d_in[11];
    const float* fc2_w   = (const float*)d_in[12];
    const float* fc2_b   = (const float*)d_in[13];
    float* out = (float*)d_out;

    int M = in_sizes[0] / C_DIM;   // 4096
    int Nb = 2;
    int T = M / Nb;                // 2048

    float *p_h, *p_qkv, *p_att, *p_x2, *p_m1;
    cudaGetSymbolAddress((void**)&p_h,   g_h);
    cudaGetSymbolAddress((void**)&p_qkv, g_qkv);
    cudaGetSymbolAddress((void**)&p_att, g_att);
    cudaGetSymbolAddress((void**)&p_x2,  g_x2);
    cudaGetSymbolAddress((void**)&p_m1,  g_m1);

    // 1) h = LN1(x)
    ln_kernel<<<M, 128>>>(x, norm1_w, norm1_b, p_h);

    // 2) qkv = h @ qkv_w^T + qkv_b        [M,1536]
    sgemm_kernel<false, false><<<dim3(QKV_DIM / 128, M / 128), 256>>>(
        p_h, qkv_w, qkv_b, nullptr, p_qkv, M, QKV_DIM, C_DIM);

    // 3) windowed attention -> g_att      [M,512]
    attn_kernel<<<dim3(T, Nb), 256>>>(p_qkv, relbias, p_att, T);

    // 4) x2 = x + att @ proj_w^T + proj_b [M,512]
    sgemm_kernel<true, false><<<dim3(C_DIM / 128, M / 128), 256>>>(
        p_att, proj_w, proj_b, x, p_x2, M, C_DIM, C_DIM);

    // 5) h = LN2(x2)
    ln_kernel<<<M, 128>>>(p_x2, norm2_w, norm2_b, p_h);

    // 6) m1 = gelu(h @ fc1_w^T + fc1_b)   [M,2048]
    sgemm_kernel<false, true><<<dim3(HID_DIM / 128, M / 128), 256>>>(
        p_h, fc1_w, fc1_b, nullptr, p_m1, M, HID_DIM, C_DIM);

    // 7) out = x2 + m1 @ fc2_w^T + fc2_b  [M,512]
    sgemm_kernel<true, false><<<dim3(C_DIM / 128, M / 128), 256>>>(
        p_m1, fc2_w, fc2_b, p_x2, out, M, C_DIM, HID_DIM);
}

// round 2
// speedup vs baseline: 2.5411x; 2.5411x over previous
#include <cuda_runtime.h>
#include <cuda_bf16.h>
#include <math.h>
#include <stdint.h>

// ---------------------------------------------------------------------------
// Shapes: x (N=2, T=2048, C=512), H=8, hd=64, WIN=63, LEFT=31, hid=2048
// ---------------------------------------------------------------------------
#define C_DIM   512
#define HID_DIM 2048
#define QKV_DIM 1536
#define H_HEADS 8
#define HEAD_D  64
#define WIN     63
#define LEFT    31
#define M_ROWS  4096   // N*T

// GEMM tiling
#define BM 128
#define BN 128
#define BK 16
#define PAD 20          // smem row stride in floats (conflict-free, 16B-aligned)

// ---------------------------------------------------------------------------
// Scratch (static device globals: no allocation allowed)
// ---------------------------------------------------------------------------
__device__ float g_h  [M_ROWS * C_DIM];
__device__ float g_qkv[M_ROWS * QKV_DIM];
__device__ float g_att[M_ROWS * C_DIM];
__device__ float g_x2 [M_ROWS * C_DIM];
__device__ float g_m1 [M_ROWS * HID_DIM];

// ---------------------------------------------------------------------------
// Small PTX helpers
// ---------------------------------------------------------------------------
__device__ __forceinline__ void cp_async16(void* smem, const void* gmem) {
    uint32_t s = (uint32_t)__cvta_generic_to_shared(smem);
    asm volatile("cp.async.cg.shared.global [%0], [%1], 16;\n" :: "r"(s), "l"(gmem));
}
__device__ __forceinline__ void cp_commit() {
    asm volatile("cp.async.commit_group;\n");
}
__device__ __forceinline__ uint32_t f2tf32(float x) {
    uint32_t r; asm("cvt.rna.tf32.f32 %0, %1;\n" : "=r"(r) : "f"(x)); return r;
}
__device__ __forceinline__ void mma_tf32(float* c, const uint32_t* a, const uint32_t* b) {
    asm volatile(
        "mma.sync.aligned.m16n8k8.row.col.f32.tf32.tf32.f32 "
        "{%0,%1,%2,%3}, {%4,%5,%6,%7}, {%8,%9}, {%0,%1,%2,%3};\n"
        : "+f"(c[0]), "+f"(c[1]), "+f"(c[2]), "+f"(c[3])
        : "r"(a[0]), "r"(a[1]), "r"(a[2]), "r"(a[3]), "r"(b[0]), "r"(b[1]));
}

// ---------------------------------------------------------------------------
// LayerNorm: one block (128 threads) per row of 512 floats
// ---------------------------------------------------------------------------
__global__ __launch_bounds__(128) void ln_kernel(
    const float* __restrict__ x, const float* __restrict__ w,
    const float* __restrict__ b, float* __restrict__ out)
{
    int row = blockIdx.x;
    int tid = threadIdx.x;
    const float4* xr = (const float4*)(x + (size_t)row * C_DIM);
    float4 v = xr[tid];
    float s  = v.x + v.y + v.z + v.w;
    float sq = v.x*v.x + v.y*v.y + v.z*v.z + v.w*v.w;
    #pragma unroll
    for (int o = 16; o > 0; o >>= 1) {
        s  += __shfl_xor_sync(0xffffffffu, s,  o);
        sq += __shfl_xor_sync(0xffffffffu, sq, o);
    }
    __shared__ float ss[4], ssq[4];
    if ((tid & 31) == 0) { ss[tid >> 5] = s; ssq[tid >> 5] = sq; }
    __syncthreads();
    s  = ss[0]  + ss[1]  + ss[2]  + ss[3];
    sq = ssq[0] + ssq[1] + ssq[2] + ssq[3];
    float mu  = s * (1.0f / C_DIM);
    float var = sq * (1.0f / C_DIM) - mu * mu;
    float inv = rsqrtf(var + 1e-5f);
    float4 wv = ((const float4*)w)[tid];
    float4 bv = ((const float4*)b)[tid];
    float4 o;
    o.x = (v.x - mu) * inv * wv.x + bv.x;
    o.y = (v.y - mu) * inv * wv.y + bv.y;
    o.z = (v.z - mu) * inv * wv.z + bv.z;
    o.w = (v.w - mu) * inv * wv.w + bv.w;
    ((float4*)(out + (size_t)row * C_DIM))[tid] = o;
}

// ---------------------------------------------------------------------------
// TF32 tensor-core GEMM: C[M,N] = A[M,K] @ B[N,K]^T + bias (+res) (opt GELU)
// 128x128 block, BK=16, 256 threads = 8 warps (2 M x 4 N), warp tile 64x32.
// mma.m16n8k8.tf32, fp32 accumulate. cp.async double-buffered.
// Dims must be multiples of tile sizes (true for all four GEMMs here).
// ---------------------------------------------------------------------------
template<bool RES, bool GELU>
__global__ __launch_bounds__(256) void tc_gemm(
    const float* __restrict__ A, const float* __restrict__ B,
    const float* __restrict__ bias, const float* __restrict__ res,
    float* __restrict__ Cm, int M, int N, int K)
{
    __shared__ __align__(16) float smA[2][BM * PAD];
    __shared__ __align__(16) float smB[2][BN * PAD];

    const int tid    = threadIdx.x;
    const int wid    = tid >> 5;
    const int lane   = tid & 31;
    const int g      = lane >> 2;     // group id 0..7
    const int tg     = lane & 3;      // thread-in-group 0..3
    const int warp_m = wid & 1;       // 0..1  -> 64 rows
    const int warp_n = wid >> 1;      // 0..3  -> 32 cols

    const float* Ab = A + (size_t)blockIdx.y * BM * K;
    const float* Bb = B + (size_t)blockIdx.x * BN * K;

    float acc[4][4][4];
    #pragma unroll
    for (int mt = 0; mt < 4; mt++)
        #pragma unroll
        for (int nt = 0; nt < 4; nt++)
            #pragma unroll
            for (int i = 0; i < 4; i++) acc[mt][nt][i] = 0.0f;

    // chunk loader: 128 rows x 16 floats per matrix = 512 float4; 2 per thread
    auto load_chunk = [&](int buf, int k0) {
        #pragma unroll
        for (int it = 0; it < 2; ++it) {
            int i = tid + it * 256;
            int r = i >> 2;
            int q = (i & 3) << 2;
            cp_async16(&smA[buf][r * PAD + q], Ab + (size_t)r * K + k0 + q);
            cp_async16(&smB[buf][r * PAD + q], Bb + (size_t)r * K + k0 + q);
        }
    };

    const int nch = K / BK;
    load_chunk(0, 0);
    cp_commit();

    for (int c = 0; c < nch; ++c) {
        if (c + 1 < nch) {
            load_chunk((c + 1) & 1, (c + 1) * BK);
            cp_commit();
            asm volatile("cp.async.wait_group 1;\n");
        } else {
            asm volatile("cp.async.wait_group 0;\n");
        }
        __syncthreads();

        const float* sa = smA[c & 1];
        const float* sb = smB[c & 1];

        #pragma unroll
        for (int ks = 0; ks < 2; ++ks) {
            const int k0 = ks * 8;
            uint32_t af[4][4], bf[4][2];
            #pragma unroll
            for (int mt = 0; mt < 4; ++mt) {
                const float* p = sa + (warp_m * 64 + mt * 16 + g) * PAD + k0;
                af[mt][0] = f2tf32(p[tg]);
                af[mt][1] = f2tf32(p[8 * PAD + tg]);
                af[mt][2] = f2tf32(p[tg + 4]);
                af[mt][3] = f2tf32(p[8 * PAD + tg + 4]);
            }
            #pragma unroll
            for (int nt = 0; nt < 4; ++nt) {
                const float* p = sb + (warp_n * 32 + nt * 8 + g) * PAD + k0;
                bf[nt][0] = f2tf32(p[tg]);
                bf[nt][1] = f2tf32(p[tg + 4]);
            }
            #pragma unroll
            for (int mt = 0; mt < 4; ++mt)
                #pragma unroll
                for (int nt = 0; nt < 4; ++nt)
                    mma_tf32(acc[mt][nt], af[mt], bf[nt]);
        }
        __syncthreads();
    }

    // epilogue
    const int row_base = blockIdx.y * BM + warp_m * 64;
    const int col_base = blockIdx.x * BN + warp_n * 32;
    #pragma unroll
    for (int mt = 0; mt < 4; ++mt) {
        #pragma unroll
        for (int nt = 0; nt < 4; ++nt) {
            int r0 = row_base + mt * 16 + g;
            int c0 = col_base + nt * 8 + 2 * tg;
            float b0 = bias[c0], b1 = bias[c0 + 1];
            #pragma unroll
            for (int half = 0; half < 2; ++half) {
                int r = r0 + half * 8;
                float v0 = acc[mt][nt][half * 2 + 0] + b0;
                float v1 = acc[mt][nt][half * 2 + 1] + b1;
                size_t off = (size_t)r * N + c0;
                if (RES) {
                    float2 rv = *(const float2*)(res + off);
                    v0 += rv.x; v1 += rv.y;
                }
                if (GELU) {
                    v0 = 0.5f * v0 * (1.0f + erff(v0 * 0.70710678118654752f));
                    v1 = 0.5f * v1 * (1.0f + erff(v1 * 0.70710678118654752f));
                }
                float2 ov; ov.x = v0; ov.y = v1;
                *(float2*)(Cm + off) = ov;
            }
        }
    }
}

// ---------------------------------------------------------------------------
// Windowed attention. grid(T, Nbatch), 256 threads = 8 warps (one per head).
// ---------------------------------------------------------------------------
__global__ __launch_bounds__(256) void attn_kernel(
    const float* __restrict__ qkv, const float* __restrict__ rel_bias,
    float* __restrict__ out, int T)
{
    int t = blockIdx.x;
    int n = blockIdx.y;
    int tid  = threadIdx.x;
    int h    = tid >> 5;
    int lane = tid & 31;

    __shared__ __align__(16) float smq[512];
    size_t rowbase = (size_t)n * T + t;
    const float* qrow = qkv + rowbase * QKV_DIM;
    smq[tid]       = qrow[tid]       * 0.125f;
    smq[tid + 256] = qrow[tid + 256] * 0.125f;
    __syncthreads();

    const float4* q4 = (const float4*)(smq + h * HEAD_D);

    float p[2];
    float mx = -1e30f;
    #pragma unroll
    for (int i = 0; i < 2; i++) {
        int w = lane + i * 32;
        float sc = -1e30f;
        if (w < WIN) {
            float bias = rel_bias[h * WIN + w];
            int pos = t - LEFT + w;
            if (pos >= 0 && pos < T) {
                const float4* k4 = (const float4*)(qkv +
                    ((size_t)n * T + pos) * QKV_DIM + C_DIM + h * HEAD_D);
                float dot = 0.0f;
                #pragma unroll
                for (int d = 0; d < 16; d++) {
                    float4 kk = k4[d];
                    float4 qq = q4[d];
                    dot += qq.x * kk.x + qq.y * kk.y + qq.z * kk.z + qq.w * kk.w;
                }
                sc = dot + bias;
            } else {
                sc = bias - 100.0f;
            }
        }
        p[i] = sc;
        mx = fmaxf(mx, sc);
    }
    #pragma unroll
    for (int o = 16; o > 0; o >>= 1)
        mx = fmaxf(mx, __shfl_xor_sync(0xffffffffu, mx, o));

    float e0 = expf(p[0] - mx);
    float e1 = (lane < WIN - 32) ? expf(p[1] - mx) : 0.0f;
    float sum = e0 + e1;
    #pragma unroll
    for (int o = 16; o > 0; o >>= 1)
        sum += __shfl_xor_sync(0xffffffffu, sum, o);
    float rinv = 1.0f / sum;
    p[0] = e0 * rinv;
    p[1] = e1 * rinv;

    float acc0 = 0.0f, acc1 = 0.0f;
    #pragma unroll
    for (int w = 0; w < WIN; w++) {
        float a = __shfl_sync(0xffffffffu, p[w >> 5], w & 31);
        int pos = t - LEFT + w;
        if (pos >= 0 && pos < T) {
            const float* vrow = qkv + ((size_t)n * T + pos) * QKV_DIM
                                + 2 * C_DIM + h * HEAD_D;
            acc0 += a * vrow[lane];
            acc1 += a * vrow[lane + 32];
        }
    }
    float* orow = out + rowbase * C_DIM + h * HEAD_D;
    orow[lane]      = acc0;
    orow[lane + 32] = acc1;
}

// ---------------------------------------------------------------------------
// Launch
// ---------------------------------------------------------------------------
extern "C" void kernel_launch(void* const* d_in, const int* in_sizes, int n_in,
                              void* d_out, int out_size)
{
    const float* x       = (const float*)d_in[0];
    const float* norm1_w = (const float*)d_in[1];
    const float* norm1_b = (const float*)d_in[2];
    const float* qkv_w   = (const float*)d_in[3];
    const float* qkv_b   = (const float*)d_in[4];
    const float* relbias = (const float*)d_in[5];
    const float* proj_w  = (const float*)d_in[6];
    const float* proj_b  = (const float*)d_in[7];
    const float* norm2_w = (const float*)d_in[8];
    const float* norm2_b = (const float*)d_in[9];
    const float* fc1_w   = (const float*)d_in[10];
    const float* fc1_b   = (const float*)d_in[11];
    const float* fc2_w   = (const float*)d_in[12];
    const float* fc2_b   = (const float*)d_in[13];
    float* out = (float*)d_out;

    int M = in_sizes[0] / C_DIM;   // 4096
    int Nb = 2;
    int T = M / Nb;                // 2048

    float *p_h, *p_qkv, *p_att, *p_x2, *p_m1;
    cudaGetSymbolAddress((void**)&p_h,   g_h);
    cudaGetSymbolAddress((void**)&p_qkv, g_qkv);
    cudaGetSymbolAddress((void**)&p_att, g_att);
    cudaGetSymbolAddress((void**)&p_x2,  g_x2);
    cudaGetSymbolAddress((void**)&p_m1,  g_m1);

    // 1) h = LN1(x)
    ln_kernel<<<M, 128>>>(x, norm1_w, norm1_b, p_h);

    // 2) qkv = h @ qkv_w^T + qkv_b        [M,1536]
    tc_gemm<false, false><<<dim3(QKV_DIM / BN, M / BM), 256>>>(
        p_h, qkv_w, qkv_b, nullptr, p_qkv, M, QKV_DIM, C_DIM);

    // 3) windowed attention -> g_att      [M,512]
    attn_kernel<<<dim3(T, Nb), 256>>>(p_qkv, relbias, p_att, T);

    // 4) x2 = x + att @ proj_w^T + proj_b [M,512]
    tc_gemm<true, false><<<dim3(C_DIM / BN, M / BM), 256>>>(
        p_att, proj_w, proj_b, x, p_x2, M, C_DIM, C_DIM);

    // 5) h = LN2(x2)
    ln_kernel<<<M, 128>>>(p_x2, norm2_w, norm2_b, p_h);

    // 6) m1 = gelu(h @ fc1_w^T + fc1_b)   [M,2048]
    tc_gemm<false, true><<<dim3(HID_DIM / BN, M / BM), 256>>>(
        p_h, fc1_w, fc1_b, nullptr, p_m1, M, HID_DIM, C_DIM);

    // 7) out = x2 + m1 @ fc2_w^T + fc2_b  [M,512]
    tc_gemm<true, false><<<dim3(C_DIM / BN, M / BM), 256>>>(
        p_m1, fc2_w, fc2_b, p_x2, out, M, C_DIM, HID_DIM);
}

// round 4
// speedup vs baseline: 3.1845x; 1.2532x over previous
#include <cuda_runtime.h>
#include <math.h>
#include <stdint.h>

// ---------------------------------------------------------------------------
// Shapes: x (N=2, T=2048, C=512), H=8, hd=64, WIN=63, LEFT=31, hid=2048
// ---------------------------------------------------------------------------
#define C_DIM   512
#define HID_DIM 2048
#define QKV_DIM 1536
#define HEAD_D  64
#define WIN     63
#define LEFT    31
#define M_ROWS  4096

#define PAD 20          // GEMM smem row stride (floats)

// attention tiling
#define ATT_TT   64                 // tokens per block
#define ATT_SPAN (ATT_TT + WIN - 1) // 126 window rows
#define ATT_LD   65                 // smem row stride (floats), conflict-free

// ---------------------------------------------------------------------------
// Scratch
// ---------------------------------------------------------------------------
__device__ float g_h  [M_ROWS * C_DIM];
__device__ float g_qkv[M_ROWS * QKV_DIM];
__device__ float g_att[M_ROWS * C_DIM];
__device__ float g_x2 [M_ROWS * C_DIM];
__device__ float g_m1 [M_ROWS * HID_DIM];

// ---------------------------------------------------------------------------
// PTX helpers
// ---------------------------------------------------------------------------
__device__ __forceinline__ void cp_async16(void* smem, const void* gmem) {
    uint32_t s = (uint32_t)__cvta_generic_to_shared(smem);
    asm volatile("cp.async.cg.shared.global [%0], [%1], 16;\n" :: "r"(s), "l"(gmem));
}
__device__ __forceinline__ uint32_t f2tf32(float x) {
    uint32_t r; asm("cvt.rna.tf32.f32 %0, %1;\n" : "=r"(r) : "f"(x)); return r;
}
__device__ __forceinline__ void mma_tf32(float* c, const uint32_t* a, const uint32_t* b) {
    asm volatile(
        "mma.sync.aligned.m16n8k8.row.col.f32.tf32.tf32.f32 "
        "{%0,%1,%2,%3}, {%4,%5,%6,%7}, {%8,%9}, {%0,%1,%2,%3};\n"
        : "+f"(c[0]), "+f"(c[1]), "+f"(c[2]), "+f"(c[3])
        : "r"(a[0]), "r"(a[1]), "r"(a[2]), "r"(a[3]), "r"(b[0]), "r"(b[1]));
}

// ---------------------------------------------------------------------------
// LayerNorm: one block (128 threads) per row of 512 floats
// ---------------------------------------------------------------------------
__global__ __launch_bounds__(128) void ln_kernel(
    const float* __restrict__ x, const float* __restrict__ w,
    const float* __restrict__ b, float* __restrict__ out)
{
    int row = blockIdx.x;
    int tid = threadIdx.x;
    const float4* xr = (const float4*)(x + (size_t)row * C_DIM);
    float4 v = xr[tid];
    float s  = v.x + v.y + v.z + v.w;
    float sq = v.x*v.x + v.y*v.y + v.z*v.z + v.w*v.w;
    #pragma unroll
    for (int o = 16; o > 0; o >>= 1) {
        s  += __shfl_xor_sync(0xffffffffu, s,  o);
        sq += __shfl_xor_sync(0xffffffffu, sq, o);
    }
    __shared__ float ss[4], ssq[4];
    if ((tid & 31) == 0) { ss[tid >> 5] = s; ssq[tid >> 5] = sq; }
    __syncthreads();
    s  = ss[0]  + ss[1]  + ss[2]  + ss[3];
    sq = ssq[0] + ssq[1] + ssq[2] + ssq[3];
    float mu  = s * (1.0f / C_DIM);
    float var = sq * (1.0f / C_DIM) - mu * mu;
    float inv = rsqrtf(var + 1e-5f);
    float4 wv = ((const float4*)w)[tid];
    float4 bv = ((const float4*)b)[tid];
    float4 o;
    o.x = (v.x - mu) * inv * wv.x + bv.x;
    o.y = (v.y - mu) * inv * wv.y + bv.y;
    o.z = (v.z - mu) * inv * wv.z + bv.z;
    o.w = (v.w - mu) * inv * wv.w + bv.w;
    ((float4*)(out + (size_t)row * C_DIM))[tid] = o;
}

// ---------------------------------------------------------------------------
// TF32 tensor-core GEMM: C[M,N] = A[M,K] @ B[N,K]^T + bias (+res) (opt GELU)
// BMx128 block, BK=16, 256 threads = 8 warps (2 M x 4 N).
// __launch_bounds__(256, 2): two CTAs per SM for latency hiding.
// ---------------------------------------------------------------------------
template<int BM_, bool RES, bool GELU>
__global__ __launch_bounds__(256, 2) void tc_gemm(
    const float* __restrict__ A, const float* __restrict__ B,
    const float* __restrict__ bias, const float* __restrict__ res,
    float* __restrict__ Cm, int M, int N, int K)
{
    constexpr int BN = 128;
    constexpr int MT = BM_ / 32;     // 16-row m-tiles per warp

    __shared__ __align__(16) float smA[2][BM_ * PAD];
    __shared__ __align__(16) float smB[2][BN * PAD];

    const int tid    = threadIdx.x;
    const int wid    = tid >> 5;
    const int lane   = tid & 31;
    const int g      = lane >> 2;
    const int tg     = lane & 3;
    const int warp_m = wid & 1;
    const int warp_n = wid >> 1;

    const float* Ab = A + (size_t)blockIdx.y * BM_ * K;
    const float* Bb = B + (size_t)blockIdx.x * BN * K;

    float acc[MT][4][4];
    #pragma unroll
    for (int mt = 0; mt < MT; mt++)
        #pragma unroll
        for (int nt = 0; nt < 4; nt++)
            #pragma unroll
            for (int i = 0; i < 4; i++) acc[mt][nt][i] = 0.0f;

    auto load_chunk = [&](int buf, int k0) {
        #pragma unroll
        for (int it = 0; it < BM_ * 4 / 256; ++it) {
            int i = tid + it * 256;
            int r = i >> 2;
            int q = (i & 3) << 2;
            cp_async16(&smA[buf][r * PAD + q], Ab + (size_t)r * K + k0 + q);
        }
        #pragma unroll
        for (int it = 0; it < 2; ++it) {
            int i = tid + it * 256;
            int r = i >> 2;
            int q = (i & 3) << 2;
            cp_async16(&smB[buf][r * PAD + q], Bb + (size_t)r * K + k0 + q);
        }
    };

    const int nch = K / 16;
    load_chunk(0, 0);
    asm volatile("cp.async.commit_group;");

    for (int c = 0; c < nch; ++c) {
        if (c + 1 < nch) {
            load_chunk((c + 1) & 1, (c + 1) * 16);
            asm volatile("cp.async.commit_group;");
            asm volatile("cp.async.wait_group 1;");
        } else {
            asm volatile("cp.async.wait_group 0;");
        }
        __syncthreads();

        const float* sa = smA[c & 1];
        const float* sb = smB[c & 1];

        #pragma unroll
        for (int ks = 0; ks < 2; ++ks) {
            const int k0 = ks * 8;
            uint32_t af[MT][4], bf[4][2];
            #pragma unroll
            for (int mt = 0; mt < MT; ++mt) {
                const float* p = sa + (warp_m * (BM_ / 2) + mt * 16 + g) * PAD + k0;
                af[mt][0] = f2tf32(p[tg]);
                af[mt][1] = f2tf32(p[8 * PAD + tg]);
                af[mt][2] = f2tf32(p[tg + 4]);
                af[mt][3] = f2tf32(p[8 * PAD + tg + 4]);
            }
            #pragma unroll
            for (int nt = 0; nt < 4; ++nt) {
                const float* p = sb + (warp_n * 32 + nt * 8 + g) * PAD + k0;
                bf[nt][0] = f2tf32(p[tg]);
                bf[nt][1] = f2tf32(p[tg + 4]);
            }
            #pragma unroll
            for (int mt = 0; mt < MT; ++mt)
                #pragma unroll
                for (int nt = 0; nt < 4; ++nt)
                    mma_tf32(acc[mt][nt], af[mt], bf[nt]);
        }
        __syncthreads();
    }

    const int row_base = blockIdx.y * BM_ + warp_m * (BM_ / 2);
    const int col_base = blockIdx.x * BN + warp_n * 32;
    #pragma unroll
    for (int mt = 0; mt < MT; ++mt) {
        #pragma unroll
        for (int nt = 0; nt < 4; ++nt) {
            int r0 = row_base + mt * 16 + g;
            int c0 = col_base + nt * 8 + 2 * tg;
            float b0 = bias[c0], b1 = bias[c0 + 1];
            #pragma unroll
            for (int half = 0; half < 2; ++half) {
                int r = r0 + half * 8;
                float v0 = acc[mt][nt][half * 2 + 0] + b0;
                float v1 = acc[mt][nt][half * 2 + 1] + b1;
                size_t off = (size_t)r * N + c0;
                if (RES) {
                    float2 rv = *(const float2*)(res + off);
                    v0 += rv.x; v1 += rv.y;
                }
                if (GELU) {
                    v0 = 0.5f * v0 * (1.0f + erff(v0 * 0.70710678118654752f));
                    v1 = 0.5f * v1 * (1.0f + erff(v1 * 0.70710678118654752f));
                }
                float2 ov; ov.x = v0; ov.y = v1;
                *(float2*)(Cm + off) = ov;
            }
        }
    }
}

// ---------------------------------------------------------------------------
// Tiled windowed attention: block = 64 tokens x 1 head.
// K/V window (126 rows x 64) staged in smem once, reused by all tokens.
// grid (T/64, H, N), 256 threads = 8 warps, each warp does 8 tokens.
// ---------------------------------------------------------------------------
__global__ __launch_bounds__(256) void attn_kernel(
    const float* __restrict__ qkv, const float* __restrict__ rel_bias,
    float* __restrict__ out, int T)
{
    const int t0 = blockIdx.x * ATT_TT;
    const int h  = blockIdx.y;
    const int n  = blockIdx.z;
    const int tid  = threadIdx.x;
    const int wid  = tid >> 5;
    const int lane = tid & 31;

    extern __shared__ __align__(16) float sm[];
    float* sk = sm;                          // [126][65]
    float* sv = sk + ATT_SPAN * ATT_LD;      // [126][65]
    float* sq = sv + ATT_SPAN * ATT_LD;      // [64][65]

    // load K/V window rows: global pos = t0 - LEFT + j, j in [0,126)
    for (int i = tid; i < ATT_SPAN * 16; i += 256) {
        int j  = i >> 4;
        int f4 = (i & 15) << 2;
        int pos = t0 - LEFT + j;
        float4 kv, vv;
        if (pos >= 0 && pos < T) {
            const float* base = qkv + ((size_t)n * T + pos) * QKV_DIM + h * HEAD_D;
            kv = *(const float4*)(base + C_DIM + f4);
            vv = *(const float4*)(base + 2 * C_DIM + f4);
        } else {
            kv = make_float4(0.f, 0.f, 0.f, 0.f);
            vv = make_float4(0.f, 0.f, 0.f, 0.f);
        }
        float* kd = sk + j * ATT_LD + f4;
        float* vd = sv + j * ATT_LD + f4;
        kd[0] = kv.x; kd[1] = kv.y; kd[2] = kv.z; kd[3] = kv.w;
        vd[0] = vv.x; vd[1] = vv.y; vd[2] = vv.z; vd[3] = vv.w;
    }
    // load q tile (scaled)
    for (int i = tid; i < ATT_TT * 16; i += 256) {
        int j  = i >> 4;
        int f4 = (i & 15) << 2;
        const float* base = qkv + ((size_t)n * T + t0 + j) * QKV_DIM + h * HEAD_D;
        float4 qv = *(const float4*)(base + f4);
        float* qd = sq + j * ATT_LD + f4;
        qd[0] = qv.x * 0.125f; qd[1] = qv.y * 0.125f;
        qd[2] = qv.z * 0.125f; qd[3] = qv.w * 0.125f;
    }
    __syncthreads();

    const float bias0 = rel_bias[h * WIN + lane];
    const float bias1 = (lane < WIN - 32) ? rel_bias[h * WIN + lane + 32] : 0.0f;

    #pragma unroll 1
    for (int tt = 0; tt < 8; ++tt) {
        const int tok = wid * 8 + tt;
        const int t   = t0 + tok;
        const float* qrow = sq + tok * ATT_LD;

        // scores: lane owns w = lane and w = lane+32
        float p0, p1;
        {
            int pos = t - LEFT + lane;
            if (pos >= 0 && pos < T) {
                const float* kr = sk + (tok + lane) * ATT_LD;
                float dot = 0.f;
                #pragma unroll
                for (int d = 0; d < HEAD_D; d += 4) {
                    dot += qrow[d]   * kr[d]   + qrow[d+1] * kr[d+1]
                         + qrow[d+2] * kr[d+2] + qrow[d+3] * kr[d+3];
                }
                p0 = dot + bias0;
            } else {
                p0 = bias0 - 100.0f;
            }
        }
        if (lane < WIN - 32) {
            int pos = t - LEFT + lane + 32;
            if (pos >= 0 && pos < T) {
                const float* kr = sk + (tok + lane + 32) * ATT_LD;
                float dot = 0.f;
                #pragma unroll
                for (int d = 0; d < HEAD_D; d += 4) {
                    dot += qrow[d]   * kr[d]   + qrow[d+1] * kr[d+1]
                         + qrow[d+2] * kr[d+2] + qrow[d+3] * kr[d+3];
                }
                p1 = dot + bias1;
            } else {
                p1 = bias1 - 100.0f;
            }
        } else {
            p1 = -1e30f;
        }

        float mx = fmaxf(p0, p1);
        #pragma unroll
        for (int o = 16; o > 0; o >>= 1)
            mx = fmaxf(mx, __shfl_xor_sync(0xffffffffu, mx, o));
        float e0 = expf(p0 - mx);
        float e1 = (lane < WIN - 32) ? expf(p1 - mx) : 0.0f;
        float sum = e0 + e1;
        #pragma unroll
        for (int o = 16; o > 0; o >>= 1)
            sum += __shfl_xor_sync(0xffffffffu, sum, o);
        float rinv = 1.0f / sum;
        e0 *= rinv; e1 *= rinv;

        // PV: out[d] = sum_w a_w * v[tok+w][d], lanes own dims lane, lane+32
        float acc0 = 0.f, acc1 = 0.f;
        #pragma unroll
        for (int w = 0; w < WIN; ++w) {
            float a = __shfl_sync(0xffffffffu, (w < 32) ? e0 : e1, w & 31);
            const float* vr = sv + (tok + w) * ATT_LD;
            acc0 += a * vr[lane];
            acc1 += a * vr[lane + 32];
        }
        float* orow = out + ((size_t)n * T + t) * C_DIM + h * HEAD_D;
        orow[lane]      = acc0;
        orow[lane + 32] = acc1;
    }
}

// ---------------------------------------------------------------------------
// Launch
// ---------------------------------------------------------------------------
extern "C" void kernel_launch(void* const* d_in, const int* in_sizes, int n_in,
                              void* d_out, int out_size)
{
    const float* x       = (const float*)d_in[0];
    const float* norm1_w = (const float*)d_in[1];
    const float* norm1_b = (const float*)d_in[2];
    const float* qkv_w   = (const float*)d_in[3];
    const float* qkv_b   = (const float*)d_in[4];
    const float* relbias = (const float*)d_in[5];
    const float* proj_w  = (const float*)d_in[6];
    const float* proj_b  = (const float*)d_in[7];
    const float* norm2_w = (const float*)d_in[8];
    const float* norm2_b = (const float*)d_in[9];
    const float* fc1_w   = (const float*)d_in[10];
    const float* fc1_b   = (const float*)d_in[11];
    const float* fc2_w   = (const float*)d_in[12];
    const float* fc2_b   = (const float*)d_in[13];
    float* out = (float*)d_out;

    int M = in_sizes[0] / C_DIM;   // 4096
    int Nb = 2;
    int T = M / Nb;                // 2048

    float *p_h, *p_qkv, *p_att, *p_x2, *p_m1;
    cudaGetSymbolAddress((void**)&p_h,   g_h);
    cudaGetSymbolAddress((void**)&p_qkv, g_qkv);
    cudaGetSymbolAddress((void**)&p_att, g_att);
    cudaGetSymbolAddress((void**)&p_x2,  g_x2);
    cudaGetSymbolAddress((void**)&p_m1,  g_m1);

    const int ATT_SMEM = (2 * ATT_SPAN * ATT_LD + ATT_TT * ATT_LD) * 4; // 82160
    cudaFuncSetAttribute(attn_kernel,
        cudaFuncAttributeMaxDynamicSharedMemorySize, ATT_SMEM);

    // 1) h = LN1(x)
    ln_kernel<<<M, 128>>>(x, norm1_w, norm1_b, p_h);

    // 2) qkv = h @ qkv_w^T + qkv_b        [M,1536]
    tc_gemm<128, false, false><<<dim3(QKV_DIM / 128, M / 128), 256>>>(
        p_h, qkv_w, qkv_b, nullptr, p_qkv, M, QKV_DIM, C_DIM);

    // 3) windowed attention -> g_att      [M,512]
    attn_kernel<<<dim3(T / ATT_TT, 8, Nb), 256, ATT_SMEM>>>(
        p_qkv, relbias, p_att, T);

    // 4) x2 = x + att @ proj_w^T + proj_b [M,512]
    tc_gemm<64, true, false><<<dim3(C_DIM / 128, M / 64), 256>>>(
        p_att, proj_w, proj_b, x, p_x2, M, C_DIM, C_DIM);

    // 5) h = LN2(x2)
    ln_kernel<<<M, 128>>>(p_x2, norm2_w, norm2_b, p_h);

    // 6) m1 = gelu(h @ fc1_w^T + fc1_b)   [M,2048]
    tc_gemm<128, false, true><<<dim3(HID_DIM / 128, M / 128), 256>>>(
        p_h, fc1_w, fc1_b, nullptr, p_m1, M, HID_DIM, C_DIM);

    // 7) out = x2 + m1 @ fc2_w^T + fc2_b  [M,512]
    tc_gemm<64, true, false><<<dim3(C_DIM / 128, M / 64), 256>>>(
        p_m1, fc2_w, fc2_b, p_x2, out, M, C_DIM, HID_DIM);
}